// round 11
// baseline (speedup 1.0000x reference)
#include <cuda_runtime.h>
#include <cuda_bf16.h>
#include <math.h>

// ---------------------------------------------------------------------------
// Problem constants
// ---------------------------------------------------------------------------
#define L1   10752
#define NF   21
#define L2   769
#define IMG  257
#define LTXT 512          // L2 - IMG
#define Hd   1536
#define NH   12
#define Dh   128
#define L3   32
#define CAd  768
#define EPSV 1e-6f

// ---------------------------------------------------------------------------
// Scratch (static __device__ globals — allocation-free per harness rules)
// ---------------------------------------------------------------------------
__device__ float g_Q   [(size_t)L1 * Hd];
__device__ float g_K   [(size_t)LTXT * Hd];
__device__ float g_Kimg[(size_t)IMG * Hd];

__device__ __nv_bfloat16 g_xh [(size_t)L1 * Hd];
__device__ __nv_bfloat16 g_xl [(size_t)L1 * Hd];
__device__ __nv_bfloat16 g_cth[(size_t)L2 * Hd];
__device__ __nv_bfloat16 g_ctl[(size_t)L2 * Hd];
__device__ __nv_bfloat16 g_aph[(size_t)NF * L3 * CAd];
__device__ __nv_bfloat16 g_apl[(size_t)NF * L3 * CAd];
__device__ __nv_bfloat16 g_Wh [6][(size_t)Hd * Hd];   // q,k,v,ki,vi,o
__device__ __nv_bfloat16 g_Wl [6][(size_t)Hd * Hd];
__device__ __nv_bfloat16 g_Wph[2][(size_t)Hd * CAd];  // kp,vp
__device__ __nv_bfloat16 g_Wpl[2][(size_t)Hd * CAd];
__device__ __nv_bfloat16 g_Ch [(size_t)L1 * Hd];
__device__ __nv_bfloat16 g_Cl [(size_t)L1 * Hd];

__device__ __nv_bfloat16 g_Qh [(size_t)L1 * Hd];
__device__ __nv_bfloat16 g_Ql [(size_t)L1 * Hd];
__device__ __nv_bfloat16 g_Kh [(size_t)LTXT * Hd];
__device__ __nv_bfloat16 g_Kl [(size_t)LTXT * Hd];
__device__ __nv_bfloat16 g_Vh [(size_t)LTXT * Hd];
__device__ __nv_bfloat16 g_Vl [(size_t)LTXT * Hd];
__device__ __nv_bfloat16 g_Kih[(size_t)IMG * Hd];
__device__ __nv_bfloat16 g_Kil[(size_t)IMG * Hd];
__device__ __nv_bfloat16 g_Vih[(size_t)IMG * Hd];
__device__ __nv_bfloat16 g_Vil[(size_t)IMG * Hd];
__device__ __nv_bfloat16 g_PKh[(size_t)NF * L3 * Hd];
__device__ __nv_bfloat16 g_PKl[(size_t)NF * L3 * Hd];
__device__ __nv_bfloat16 g_PVh[(size_t)NF * L3 * Hd];
__device__ __nv_bfloat16 g_PVl[(size_t)NF * L3 * Hd];

// ---------------------------------------------------------------------------
// Helpers
// ---------------------------------------------------------------------------
__device__ __forceinline__ unsigned pack_bf16(__nv_bfloat16 lo, __nv_bfloat16 hi)
{
    return ((unsigned)__bfloat16_as_ushort(hi) << 16) | (unsigned)__bfloat16_as_ushort(lo);
}

__device__ __forceinline__ void mma_bf16(float* d, const unsigned* a, const unsigned* b)
{
    asm volatile(
        "mma.sync.aligned.m16n8k16.row.col.f32.bf16.bf16.f32 "
        "{%0,%1,%2,%3}, {%4,%5,%6,%7}, {%8,%9}, {%0,%1,%2,%3};\n"
        : "+f"(d[0]), "+f"(d[1]), "+f"(d[2]), "+f"(d[3])
        : "r"(a[0]), "r"(a[1]), "r"(a[2]), "r"(a[3]), "r"(b[0]), "r"(b[1]));
}

__device__ __forceinline__ void ldsm_x4(unsigned* r, const void* p)
{
    unsigned addr = (unsigned)__cvta_generic_to_shared(p);
    asm volatile(
        "ldmatrix.sync.aligned.m8n8.x4.shared.b16 {%0,%1,%2,%3}, [%4];\n"
        : "=r"(r[0]), "=r"(r[1]), "=r"(r[2]), "=r"(r[3]) : "r"(addr));
}

__device__ __forceinline__ void ldsm_x4_t(unsigned* r, const void* p)
{
    unsigned addr = (unsigned)__cvta_generic_to_shared(p);
    asm volatile(
        "ldmatrix.sync.aligned.m8n8.x4.trans.shared.b16 {%0,%1,%2,%3}, [%4];\n"
        : "=r"(r[0]), "=r"(r[1]), "=r"(r[2]), "=r"(r[3]) : "r"(addr));
}

__device__ __forceinline__ void cp_async16(void* dst, const void* src, int szbytes)
{
    unsigned d = (unsigned)__cvta_generic_to_shared(dst);
    asm volatile("cp.async.cg.shared.global [%0], [%1], 16, %2;\n"
                 :: "r"(d), "l"(src), "r"(szbytes));
}

__device__ __forceinline__ void split_pack2(float a, float b, unsigned& hi, unsigned& lo)
{
    __nv_bfloat16 ha = __float2bfloat16_rn(a);
    __nv_bfloat16 hb = __float2bfloat16_rn(b);
    hi = pack_bf16(ha, hb);
    lo = pack_bf16(__float2bfloat16_rn(a - __bfloat162float(ha)),
                   __float2bfloat16_rn(b - __bfloat162float(hb)));
}

// ---------------------------------------------------------------------------
// Merged elementwise split: all fp32 -> (hi, lo) bf16 passes in ONE launch
// ---------------------------------------------------------------------------
#define NSPLIT 11
struct SplitArgs {
    const float4* src[NSPLIT];
    uint2* hi[NSPLIT];
    uint2* lo[NSPLIT];
    int end[NSPLIT];          // prefix-sum (exclusive end) in float4 units
};

__global__ __launch_bounds__(256) void split_all_kernel(SplitArgs a)
{
    int i = blockIdx.x * 256 + threadIdx.x;
    if (i >= a.end[NSPLIT - 1]) return;
    int s = 0;
    while (i >= a.end[s]) s++;
    int base = (s == 0) ? 0 : a.end[s - 1];
    int li = i - base;
    float4 v = a.src[s][li];
    unsigned h0, l0, h1, l1;
    split_pack2(v.x, v.y, h0, l0);
    split_pack2(v.z, v.w, h1, l1);
    a.hi[s][li] = make_uint2(h0, h1);
    a.lo[s][li] = make_uint2(l0, l1);
}

// ---------------------------------------------------------------------------
// Merged RMSNorm (Q / K / Kimg) + hi/lo bf16 split output, ONE launch
// ---------------------------------------------------------------------------
__global__ __launch_bounds__(256) void rmsnorm_all(
    const float* __restrict__ XQ, const float* __restrict__ wq,
    __nv_bfloat16* __restrict__ QH, __nv_bfloat16* __restrict__ QL,
    const float* __restrict__ XK, const float* __restrict__ wk,
    __nv_bfloat16* __restrict__ KH, __nv_bfloat16* __restrict__ KL,
    const float* __restrict__ XI, const float* __restrict__ wi,
    __nv_bfloat16* __restrict__ IH, __nv_bfloat16* __restrict__ IL)
{
    int row = blockIdx.x;
    const float *X, *w;
    __nv_bfloat16 *H, *Lo;
    if (row < L1)              { X = XQ; w = wq; H = QH; Lo = QL; }
    else if (row < L1 + LTXT)  { row -= L1; X = XK; w = wk; H = KH; Lo = KL; }
    else                       { row -= L1 + LTXT; X = XI; w = wi; H = IH; Lo = IL; }

    const float* x = X + (size_t)row * Hd;
    const int tid = threadIdx.x;

    float v[6];
    float ss = 0.f;
#pragma unroll
    for (int i = 0; i < 6; i++) {
        v[i] = x[tid + i * 256];
        ss = fmaf(v[i], v[i], ss);
    }
#pragma unroll
    for (int o = 16; o > 0; o >>= 1) ss += __shfl_xor_sync(0xffffffffu, ss, o);

    __shared__ float warp_s[8];
    __shared__ float s_scale;
    if ((tid & 31) == 0) warp_s[tid >> 5] = ss;
    __syncthreads();
    if (tid < 8) {
        float t = warp_s[tid];
#pragma unroll
        for (int o = 4; o > 0; o >>= 1) t += __shfl_xor_sync(0xffu, t, o);
        if (tid == 0) s_scale = rsqrtf(t * (1.f / (float)Hd) + EPSV);
    }
    __syncthreads();
    float sc = s_scale;
#pragma unroll
    for (int i = 0; i < 6; i++) {
        int c = tid + i * 256;
        float f = v[i] * sc * w[c];
        __nv_bfloat16 h = __float2bfloat16_rn(f);
        H[(size_t)row * Hd + c]  = h;
        Lo[(size_t)row * Hd + c] = __float2bfloat16_rn(f - __bfloat162float(h));
    }
}

// ---------------------------------------------------------------------------
// Tensor-core GEMM body (bf16x3), GBK=32, cp.async double-buffered.
// All GEMMs have N = 1536 (nbx = 12). Output row stride = Hd.
// ---------------------------------------------------------------------------
#define GBM 128
#define GBN 128
#define GBK 32
#define TILE_E (GBM * GBK)      // 4096 bf16 = 8KB per tile

__device__ __forceinline__ int swz32(int r, int k)
{
    return r * GBK + ((((k >> 3) ^ (r >> 1)) & 3) << 3) + (k & 7);
}

struct GemmAcc { float a[2][8][4]; };

__device__ __forceinline__ void gemm_body(
    const __nv_bfloat16* __restrict__ Ah, const __nv_bfloat16* __restrict__ Al,
    const __nv_bfloat16* __restrict__ Bh, const __nv_bfloat16* __restrict__ Bl,
    int M, int K, int bm, int bn, GemmAcc& acc,
    __nv_bfloat16 (*s)[4][TILE_E])
{
    const int tid  = threadIdx.x;
    const int warp = tid >> 5;
    const int lane = tid & 31;
    const int wm   = warp >> 1;
    const int wn   = warp & 1;

    const int lr   = tid >> 1;            // row 0..127
    const int lcp  = (tid & 1) << 4;      // k base 0 or 16
    const int o0   = swz32(lr, lcp);
    const int o1   = swz32(lr, lcp + 8);
    const bool va  = (bm + lr) < M;
    const int  ra  = va ? (bm + lr) : 0;
    const int  rb  = bn + lr;
    const int  sza = va ? 16 : 0;

#pragma unroll
    for (int i = 0; i < 2; i++)
#pragma unroll
        for (int j = 0; j < 8; j++)
#pragma unroll
            for (int t = 0; t < 4; t++) acc.a[i][j][t] = 0.f;

    const int nt = K / GBK;

    {
        const __nv_bfloat16* pa = Ah + (size_t)ra * K + lcp;
        const __nv_bfloat16* pl = Al + (size_t)ra * K + lcp;
        const __nv_bfloat16* pb = Bh + (size_t)rb * K + lcp;
        const __nv_bfloat16* pc = Bl + (size_t)rb * K + lcp;
        cp_async16(&s[0][0][o0], pa,     sza);
        cp_async16(&s[0][0][o1], pa + 8, sza);
        cp_async16(&s[0][1][o0], pl,     sza);
        cp_async16(&s[0][1][o1], pl + 8, sza);
        cp_async16(&s[0][2][o0], pb,     16);
        cp_async16(&s[0][2][o1], pb + 8, 16);
        cp_async16(&s[0][3][o0], pc,     16);
        cp_async16(&s[0][3][o1], pc + 8, 16);
        asm volatile("cp.async.commit_group;\n" ::: "memory");
    }

    const int rfrg = lane & 15;
    const int kfo  = (lane >> 4) << 3;

    for (int t = 0; t < nt; t++) {
        if (t + 1 < nt) {
            const int st = (t + 1) & 1;
            const int k0 = (t + 1) * GBK;
            const __nv_bfloat16* pa = Ah + (size_t)ra * K + k0 + lcp;
            const __nv_bfloat16* pl = Al + (size_t)ra * K + k0 + lcp;
            const __nv_bfloat16* pb = Bh + (size_t)rb * K + k0 + lcp;
            const __nv_bfloat16* pc = Bl + (size_t)rb * K + k0 + lcp;
            cp_async16(&s[st][0][o0], pa,     sza);
            cp_async16(&s[st][0][o1], pa + 8, sza);
            cp_async16(&s[st][1][o0], pl,     sza);
            cp_async16(&s[st][1][o1], pl + 8, sza);
            cp_async16(&s[st][2][o0], pb,     16);
            cp_async16(&s[st][2][o1], pb + 8, 16);
            cp_async16(&s[st][3][o0], pc,     16);
            cp_async16(&s[st][3][o1], pc + 8, 16);
            asm volatile("cp.async.commit_group;\n" ::: "memory");
            asm volatile("cp.async.wait_group 1;\n" ::: "memory");
        } else {
            asm volatile("cp.async.wait_group 0;\n" ::: "memory");
        }
        __syncthreads();

        const __nv_bfloat16* pAh = s[t & 1][0];
        const __nv_bfloat16* pAl = s[t & 1][1];
        const __nv_bfloat16* pBh = s[t & 1][2];
        const __nv_bfloat16* pBl = s[t & 1][3];

#pragma unroll
        for (int ks = 0; ks < 2; ks++) {
            const int kf = ks * 16 + kfo;

            unsigned ah[2][4], al[2][4];
#pragma unroll
            for (int i = 0; i < 2; i++) {
                int r = wm * 32 + i * 16 + rfrg;
                ldsm_x4(ah[i], pAh + swz32(r, kf));
                ldsm_x4(al[i], pAl + swz32(r, kf));
            }

            unsigned bh[8][2], bl[8][2];
#pragma unroll
            for (int p = 0; p < 4; p++) {
                int n = wn * 64 + p * 16 + rfrg;
                unsigned tt[4];
                ldsm_x4(tt, pBh + swz32(n, kf));
                bh[p*2][0] = tt[0]; bh[p*2+1][0] = tt[1];
                bh[p*2][1] = tt[2]; bh[p*2+1][1] = tt[3];
                ldsm_x4(tt, pBl + swz32(n, kf));
                bl[p*2][0] = tt[0]; bl[p*2+1][0] = tt[1];
                bl[p*2][1] = tt[2]; bl[p*2+1][1] = tt[3];
            }

#pragma unroll
            for (int i = 0; i < 2; i++)
#pragma unroll
                for (int j = 0; j < 8; j++) {
                    mma_bf16(acc.a[i][j], ah[i], bh[j]);
                    mma_bf16(acc.a[i][j], ah[i], bl[j]);
                    mma_bf16(acc.a[i][j], al[i], bh[j]);
                }
        }
        __syncthreads();
    }
}

// ---------------------------------------------------------------------------
// Merged projection GEMM: 7 segments in one launch (Q first).
// ---------------------------------------------------------------------------
#define NGSEG 7
struct GemmSeg {
    const __nv_bfloat16 *Ah, *Al, *Bh, *Bl;
    const float* bias;
    float* Cf;                       // fp32 out (else split out)
    __nv_bfloat16 *Chp, *Clp;
    int M, K, blk_end;
};
struct GemmArgs { GemmSeg seg[NGSEG]; };

__global__ __launch_bounds__(256) void gemm_all(GemmArgs ga)
{
    __shared__ __nv_bfloat16 s[2][4][TILE_E];

    int sidx = 0;
    while ((int)blockIdx.x >= ga.seg[sidx].blk_end) sidx++;
    const GemmSeg& g = ga.seg[sidx];
    const int base  = (sidx == 0) ? 0 : ga.seg[sidx - 1].blk_end;
    const int local = blockIdx.x - base;
    const int bm = (local / 12) * GBM;
    const int bn = (local % 12) * GBN;

    GemmAcc acc;
    gemm_body(g.Ah, g.Al, g.Bh, g.Bl, g.M, g.K, bm, bn, acc, s);

    const int lane = threadIdx.x & 31;
    const int warp = threadIdx.x >> 5;
    const int wm = warp >> 1, wn = warp & 1;

#pragma unroll
    for (int i = 0; i < 2; i++) {
        int r0 = bm + wm * 32 + i * 16 + (lane >> 2);
        int r1 = r0 + 8;
#pragma unroll
        for (int j = 0; j < 8; j++) {
            int c  = bn + wn * 64 + j * 8 + (lane & 3) * 2;
            float b0 = g.bias ? g.bias[c]     : 0.f;
            float b1 = g.bias ? g.bias[c + 1] : 0.f;
            float v0 = acc.a[i][j][0] + b0, v1 = acc.a[i][j][1] + b1;
            float v2 = acc.a[i][j][2] + b0, v3 = acc.a[i][j][3] + b1;
            if (g.Cf) {
                if (r0 < g.M) {
                    g.Cf[(size_t)r0 * Hd + c]     = v0;
                    g.Cf[(size_t)r0 * Hd + c + 1] = v1;
                }
                if (r1 < g.M) {
                    g.Cf[(size_t)r1 * Hd + c]     = v2;
                    g.Cf[(size_t)r1 * Hd + c + 1] = v3;
                }
            } else {
                unsigned hi, lo;
                if (r0 < g.M) {
                    split_pack2(v0, v1, hi, lo);
                    *(unsigned*)&g.Chp[(size_t)r0 * Hd + c] = hi;
                    *(unsigned*)&g.Clp[(size_t)r0 * Hd + c] = lo;
                }
                if (r1 < g.M) {
                    split_pack2(v2, v3, hi, lo);
                    *(unsigned*)&g.Chp[(size_t)r1 * Hd + c] = hi;
                    *(unsigned*)&g.Clp[(size_t)r1 * Hd + c] = lo;
                }
            }
        }
    }
}

// Standalone GEMM for the O-projection (fp32 out).
__global__ __launch_bounds__(256) void gemm_pipe(
    const __nv_bfloat16* __restrict__ Ah, const __nv_bfloat16* __restrict__ Al,
    const __nv_bfloat16* __restrict__ Bh, const __nv_bfloat16* __restrict__ Bl,
    const float* __restrict__ bias, float* __restrict__ C,
    int M, int K)
{
    __shared__ __nv_bfloat16 s[2][4][TILE_E];
    const int bm = blockIdx.y * GBM;
    const int bn = blockIdx.x * GBN;

    GemmAcc acc;
    gemm_body(Ah, Al, Bh, Bl, M, K, bm, bn, acc, s);

    const int lane = threadIdx.x & 31;
    const int warp = threadIdx.x >> 5;
    const int wm = warp >> 1, wn = warp & 1;

#pragma unroll
    for (int i = 0; i < 2; i++) {
        int r0 = bm + wm * 32 + i * 16 + (lane >> 2);
        int r1 = r0 + 8;
#pragma unroll
        for (int j = 0; j < 8; j++) {
            int c  = bn + wn * 64 + j * 8 + (lane & 3) * 2;
            float b0 = bias ? bias[c]     : 0.f;
            float b1 = bias ? bias[c + 1] : 0.f;
            if (r0 < M) {
                C[(size_t)r0 * Hd + c]     = acc.a[i][j][0] + b0;
                C[(size_t)r0 * Hd + c + 1] = acc.a[i][j][1] + b1;
            }
            if (r1 < M) {
                C[(size_t)r1 * Hd + c]     = acc.a[i][j][2] + b0;
                C[(size_t)r1 * Hd + c + 1] = acc.a[i][j][3] + b1;
            }
        }
    }
}

// ---------------------------------------------------------------------------
// Tensor-core fused 3-phase flash attention (unchanged from R10 winner).
// ---------------------------------------------------------------------------
#define ATQ 64
#define ASTR 132
#define AQ_ELE (64 * 128)
#define AKV_ELE (32 * 128)
#define ATTN_SMEM ((2 * AQ_ELE + 8 * AKV_ELE) * 2)   // 96 KB

__device__ __forceinline__ int soff(int r, int c8)
{
    return r * 128 + (((c8) ^ (r & 7)) << 3);
}

__global__ __launch_bounds__(128) void attn_mma(
    const __nv_bfloat16* __restrict__ Qh,  const __nv_bfloat16* __restrict__ Ql,
    const __nv_bfloat16* __restrict__ Kth, const __nv_bfloat16* __restrict__ Ktl,
    const __nv_bfloat16* __restrict__ Vth, const __nv_bfloat16* __restrict__ Vtl,
    const __nv_bfloat16* __restrict__ Kih, const __nv_bfloat16* __restrict__ Kil,
    const __nv_bfloat16* __restrict__ Vih, const __nv_bfloat16* __restrict__ Vil,
    const __nv_bfloat16* __restrict__ PKh, const __nv_bfloat16* __restrict__ PKl,
    const __nv_bfloat16* __restrict__ PVh, const __nv_bfloat16* __restrict__ PVl,
    const int* __restrict__ ctx_lens, const int* __restrict__ audio_lens,
    __nv_bfloat16* __restrict__ Ch, __nv_bfloat16* __restrict__ Cl)
{
    extern __shared__ __nv_bfloat16 sm[];
    __nv_bfloat16* sQh = sm;
    __nv_bfloat16* sQl = sQh + AQ_ELE;
    __nv_bfloat16* sKV = sQl + AQ_ELE;

    const int head  = blockIdx.y;
    const int qbase = blockIdx.x * ATQ;
    const int tid   = threadIdx.x;
    const int warp  = tid >> 5;
    const int lane  = tid & 31;
    const int g     = lane >> 2;
    const int tq    = lane & 3;
    const float scale = 0.08838834764831845f;

#pragma unroll
    for (int i = 0; i < 8; i++) {
        int idx = tid + i * 128;
        int r = idx >> 4, c8 = idx & 15;
        size_t go = (size_t)(qbase + r) * Hd + head * Dh + c8 * 8;
        int so = soff(r, c8);
        *(uint4*)&sQh[so] = *(const uint4*)&Qh[go];
        *(uint4*)&sQl[so] = *(const uint4*)&Ql[go];
    }
    __syncthreads();

    float G[16][4];
#pragma unroll
    for (int n = 0; n < 16; n++)
#pragma unroll
        for (int e = 0; e < 4; e++) G[n][e] = 0.f;

    const int frame   = qbase >> 9;
    const int txt_len = ctx_lens[0];
    const int rfrg = lane & 15;
    const int chi  = lane >> 4;

    for (int phase = 0; phase < 3; phase++) {
        const __nv_bfloat16 *KH, *KL, *VH, *VL;
        int klen;
        if (phase == 0)      { KH = Kih; KL = Kil; VH = Vih; VL = Vil; klen = IMG; }
        else if (phase == 1) { KH = Kth; KL = Ktl; VH = Vth; VL = Vtl; klen = txt_len; }
        else {
            size_t fo = (size_t)frame * L3 * Hd;
            KH = PKh + fo; KL = PKl + fo; VH = PVh + fo; VL = PVl + fo;
            klen = audio_lens[frame];
        }
        const int nch = (klen + 31) >> 5;

        {
            const int cl = min(32, klen);
#pragma unroll
            for (int a = 0; a < 4; a++) {
                const __nv_bfloat16* src = (a == 0) ? KH : (a == 1) ? KL
                                         : (a == 2) ? VH : VL;
#pragma unroll
                for (int i = 0; i < 4; i++) {
                    int idx = tid + i * 128;
                    int r = idx >> 4, c8 = idx & 15;
                    int grow = (r < cl) ? r : 0;
                    cp_async16(&sKV[a * AKV_ELE + soff(r, c8)],
                               src + (size_t)grow * Hd + head * Dh + c8 * 8,
                               r < cl ? 16 : 0);
                }
            }
            asm volatile("cp.async.commit_group;\n" ::: "memory");
        }

        float m0 = -1e30f, m1 = -1e30f, l0 = 0.f, l1 = 0.f;
        float o[16][4];
#pragma unroll
        for (int n = 0; n < 16; n++)
#pragma unroll
            for (int e = 0; e < 4; e++) o[n][e] = 0.f;

        for (int c = 0; c < nch; c++) {
            const int b = c & 1;
            if (c + 1 < nch) {
                const int kb2 = (c + 1) * 32;
                const int cl2 = min(32, klen - kb2);
#pragma unroll
                for (int a = 0; a < 4; a++) {
                    const __nv_bfloat16* src = (a == 0) ? KH : (a == 1) ? KL
                                             : (a == 2) ? VH : VL;
#pragma unroll
                    for (int i = 0; i < 4; i++) {
                        int idx = tid + i * 128;
                        int r = idx >> 4, c8 = idx & 15;
                        int grow = (r < cl2) ? kb2 + r : 0;
                        cp_async16(&sKV[((b ^ 1) * 4 + a) * AKV_ELE + soff(r, c8)],
                                   src + (size_t)grow * Hd + head * Dh + c8 * 8,
                                   r < cl2 ? 16 : 0);
                    }
                }
                asm volatile("cp.async.commit_group;\n" ::: "memory");
                asm volatile("cp.async.wait_group 1;\n" ::: "memory");
            } else {
                asm volatile("cp.async.wait_group 0;\n" ::: "memory");
            }
            __syncthreads();

            const __nv_bfloat16* pKh = sKV + (b * 4 + 0) * AKV_ELE;
            const __nv_bfloat16* pKl = sKV + (b * 4 + 1) * AKV_ELE;
            const __nv_bfloat16* pVh = sKV + (b * 4 + 2) * AKV_ELE;
            const __nv_bfloat16* pVl = sKV + (b * 4 + 3) * AKV_ELE;
            const int kb = c * 32;

            float sacc[4][4];
#pragma unroll
            for (int n = 0; n < 4; n++)
#pragma unroll
                for (int e = 0; e < 4; e++) sacc[n][e] = 0.f;

#pragma unroll
            for (int ks = 0; ks < 8; ks++) {
                const int c8 = ks * 2 + chi;
                unsigned aqh[4], aql[4];
                ldsm_x4(aqh, &sQh[soff(warp * 16 + rfrg, c8)]);
                ldsm_x4(aql, &sQl[soff(warp * 16 + rfrg, c8)]);

                unsigned kbh[4][2], kbl[4][2];
#pragma unroll
                for (int p = 0; p < 2; p++) {
                    unsigned t[4];
                    ldsm_x4(t, &pKh[soff(p * 16 + rfrg, c8)]);
                    kbh[p*2][0] = t[0]; kbh[p*2+1][0] = t[1];
                    kbh[p*2][1] = t[2]; kbh[p*2+1][1] = t[3];
                    ldsm_x4(t, &pKl[soff(p * 16 + rfrg, c8)]);
                    kbl[p*2][0] = t[0]; kbl[p*2+1][0] = t[1];
                    kbl[p*2][1] = t[2]; kbl[p*2+1][1] = t[3];
                }
#pragma unroll
                for (int n = 0; n < 4; n++) {
                    mma_bf16(sacc[n], aqh, kbh[n]);
                    mma_bf16(sacc[n], aqh, kbl[n]);
                    mma_bf16(sacc[n], aql, kbh[n]);
                }
            }

            float rmax0 = -1e30f, rmax1 = -1e30f;
#pragma unroll
            for (int n = 0; n < 4; n++) {
                int colb = kb + n * 8 + tq * 2;
                bool v0 = colb < klen, v1 = (colb + 1) < klen;
                float x0 = v0 ? sacc[n][0] * scale : -1e30f;
                float x1 = v1 ? sacc[n][1] * scale : -1e30f;
                float x2 = v0 ? sacc[n][2] * scale : -1e30f;
                float x3 = v1 ? sacc[n][3] * scale : -1e30f;
                sacc[n][0] = x0; sacc[n][1] = x1; sacc[n][2] = x2; sacc[n][3] = x3;
                rmax0 = fmaxf(rmax0, fmaxf(x0, x1));
                rmax1 = fmaxf(rmax1, fmaxf(x2, x3));
            }
            rmax0 = fmaxf(rmax0, __shfl_xor_sync(0xffffffffu, rmax0, 1));
            rmax0 = fmaxf(rmax0, __shfl_xor_sync(0xffffffffu, rmax0, 2));
            rmax1 = fmaxf(rmax1, __shfl_xor_sync(0xffffffffu, rmax1, 1));
            rmax1 = fmaxf(rmax1, __shfl_xor_sync(0xffffffffu, rmax1, 2));

            float mn0 = fmaxf(m0, rmax0), mn1 = fmaxf(m1, rmax1);
            float c0 = __expf(m0 - mn0),  c1 = __expf(m1 - mn1);
            float s0 = 0.f, s1 = 0.f;
#pragma unroll
            for (int n = 0; n < 4; n++) {
                float p0 = __expf(sacc[n][0] - mn0);
                float p1 = __expf(sacc[n][1] - mn0);
                float p2 = __expf(sacc[n][2] - mn1);
                float p3 = __expf(sacc[n][3] - mn1);
                sacc[n][0] = p0; sacc[n][1] = p1; sacc[n][2] = p2; sacc[n][3] = p3;
                s0 += p0 + p1; s1 += p2 + p3;
            }
            s0 += __shfl_xor_sync(0xffffffffu, s0, 1);
            s0 += __shfl_xor_sync(0xffffffffu, s0, 2);
            s1 += __shfl_xor_sync(0xffffffffu, s1, 1);
            s1 += __shfl_xor_sync(0xffffffffu, s1, 2);
            l0 = l0 * c0 + s0; l1 = l1 * c1 + s1;
            m0 = mn0; m1 = mn1;

#pragma unroll
            for (int n = 0; n < 16; n++) {
                o[n][0] *= c0; o[n][1] *= c0;
                o[n][2] *= c1; o[n][3] *= c1;
            }

            unsigned aPh[2][4], aPl[2][4];
#pragma unroll
            for (int ks = 0; ks < 2; ks++) {
                split_pack2(sacc[2*ks][0],   sacc[2*ks][1],   aPh[ks][0], aPl[ks][0]);
                split_pack2(sacc[2*ks][2],   sacc[2*ks][3],   aPh[ks][1], aPl[ks][1]);
                split_pack2(sacc[2*ks+1][0], sacc[2*ks+1][1], aPh[ks][2], aPl[ks][2]);
                split_pack2(sacc[2*ks+1][2], sacc[2*ks+1][3], aPh[ks][3], aPl[ks][3]);
            }

#pragma unroll
            for (int ks = 0; ks < 2; ks++) {
#pragma unroll
                for (int ntp = 0; ntp < 8; ntp++) {
                    int vr = ks * 16 + ((lane >> 3) & 1) * 8 + (lane & 7);
                    int vc = ntp * 2 + (lane >> 4);
                    unsigned th[4], tl[4];
                    ldsm_x4_t(th, &pVh[soff(vr, vc)]);
                    ldsm_x4_t(tl, &pVl[soff(vr, vc)]);
                    unsigned bh0[2] = {th[0], th[1]};
                    unsigned bh1[2] = {th[2], th[3]};
                    unsigned bl0[2] = {tl[0], tl[1]};
                    unsigned bl1[2] = {tl[2], tl[3]};
                    mma_bf16(o[2*ntp],   aPh[ks], bh0);
                    mma_bf16(o[2*ntp],   aPh[ks], bl0);
                    mma_bf16(o[2*ntp],   aPl[ks], bh0);
                    mma_bf16(o[2*ntp+1], aPh[ks], bh1);
                    mma_bf16(o[2*ntp+1], aPh[ks], bl1);
                    mma_bf16(o[2*ntp+1], aPl[ks], bh1);
                }
            }
            __syncthreads();
        }

        float rl0 = 1.f / l0, rl1 = 1.f / l1;
#pragma unroll
        for (int n = 0; n < 16; n++) {
            G[n][0] += o[n][0] * rl0; G[n][1] += o[n][1] * rl0;
            G[n][2] += o[n][2] * rl1; G[n][3] += o[n][3] * rl1;
        }
    }

    float* sO = (float*)sKV;
    {
        int row0 = warp * 16 + g;
#pragma unroll
        for (int n = 0; n < 16; n++) {
            int col = n * 8 + tq * 2;
            sO[row0 * ASTR + col]           = G[n][0];
            sO[row0 * ASTR + col + 1]       = G[n][1];
            sO[(row0 + 8) * ASTR + col]     = G[n][2];
            sO[(row0 + 8) * ASTR + col + 1] = G[n][3];
        }
    }
    __syncthreads();
#pragma unroll
    for (int i = 0; i < 16; i++) {
        int idx = tid + i * 128;
        int r = idx >> 5, cb = (idx & 31) * 4;
        float f0 = sO[r * ASTR + cb + 0];
        float f1 = sO[r * ASTR + cb + 1];
        float f2 = sO[r * ASTR + cb + 2];
        float f3 = sO[r * ASTR + cb + 3];
        unsigned h0, l0u, h1, l1u;
        split_pack2(f0, f1, h0, l0u);
        split_pack2(f2, f3, h1, l1u);
        size_t go = (size_t)(qbase + r) * Hd + head * Dh + cb;
        *(uint2*)&Ch[go] = make_uint2(h0, h1);
        *(uint2*)&Cl[go] = make_uint2(l0u, l1u);
    }
}

// ---------------------------------------------------------------------------
// Launch
// ---------------------------------------------------------------------------
extern "C" void kernel_launch(void* const* d_in, const int* in_sizes, int n_in,
                              void* d_out, int out_size)
{
    const float* x          = (const float*)d_in[0];
    const float* context    = (const float*)d_in[1];
    const float* audio_proj = (const float*)d_in[2];
    const float* Wq  = (const float*)d_in[3];
    const float* bq  = (const float*)d_in[4];
    const float* Wk  = (const float*)d_in[5];
    const float* bk  = (const float*)d_in[6];
    const float* Wv  = (const float*)d_in[7];
    const float* bv  = (const float*)d_in[8];
    const float* Wki = (const float*)d_in[9];
    const float* bki = (const float*)d_in[10];
    const float* Wvi = (const float*)d_in[11];
    const float* bvi = (const float*)d_in[12];
    const float* Wo  = (const float*)d_in[13];
    const float* bo  = (const float*)d_in[14];
    const float* nq  = (const float*)d_in[15];
    const float* nk  = (const float*)d_in[16];
    const float* nki = (const float*)d_in[17];
    const float* Wkp = (const float*)d_in[18];
    const float* Wvp = (const float*)d_in[19];
    const int* ctx_lens   = (const int*)d_in[20];
    const int* audio_lens = (const int*)d_in[21];
    float* out = (float*)d_out;

    float *gQ, *gK, *gKi;
    cudaGetSymbolAddress((void**)&gQ,  g_Q);
    cudaGetSymbolAddress((void**)&gK,  g_K);
    cudaGetSymbolAddress((void**)&gKi, g_Kimg);

    __nv_bfloat16 *xh, *xl, *cth, *ctl, *aph, *apl, *Wh, *Wl, *Wph, *Wpl, *Chh, *Cll;
    cudaGetSymbolAddress((void**)&xh,  g_xh);
    cudaGetSymbolAddress((void**)&xl,  g_xl);
    cudaGetSymbolAddress((void**)&cth, g_cth);
    cudaGetSymbolAddress((void**)&ctl, g_ctl);
    cudaGetSymbolAddress((void**)&aph, g_aph);
    cudaGetSymbolAddress((void**)&apl, g_apl);
    cudaGetSymbolAddress((void**)&Wh,  g_Wh);
    cudaGetSymbolAddress((void**)&Wl,  g_Wl);
    cudaGetSymbolAddress((void**)&Wph, g_Wph);
    cudaGetSymbolAddress((void**)&Wpl, g_Wpl);
    cudaGetSymbolAddress((void**)&Chh, g_Ch);
    cudaGetSymbolAddress((void**)&Cll, g_Cl);

    __nv_bfloat16 *Qh, *Ql, *Kh, *Kl, *Vh, *Vl, *Kih, *Kil, *Vih, *Vil,
                  *PKh, *PKl, *PVh, *PVl;
    cudaGetSymbolAddress((void**)&Qh,  g_Qh);
    cudaGetSymbolAddress((void**)&Ql,  g_Ql);
    cudaGetSymbolAddress((void**)&Kh,  g_Kh);
    cudaGetSymbolAddress((void**)&Kl,  g_Kl);
    cudaGetSymbolAddress((void**)&Vh,  g_Vh);
    cudaGetSymbolAddress((void**)&Vl,  g_Vl);
    cudaGetSymbolAddress((void**)&Kih, g_Kih);
    cudaGetSymbolAddress((void**)&Kil, g_Kil);
    cudaGetSymbolAddress((void**)&Vih, g_Vih);
    cudaGetSymbolAddress((void**)&Vil, g_Vil);
    cudaGetSymbolAddress((void**)&PKh, g_PKh);
    cudaGetSymbolAddress((void**)&PKl, g_PKl);
    cudaGetSymbolAddress((void**)&PVh, g_PVh);
    cudaGetSymbolAddress((void**)&PVl, g_PVl);

    cudaFuncSetAttribute(attn_mma, cudaFuncAttributeMaxDynamicSharedMemorySize,
                         ATTN_SMEM);

    const size_t WSZ  = (size_t)Hd * Hd;
    const size_t WPSZ = (size_t)Hd * CAd;

    // ---- 1) merged split of all fp32 operands ----
    {
        SplitArgs sa;
        const float* srcs[NSPLIT] = { x, context, audio_proj,
                                      Wq, Wk, Wv, Wki, Wvi, Wo, Wkp, Wvp };
        __nv_bfloat16* his[NSPLIT] = { xh, cth, aph,
            Wh + 0 * WSZ, Wh + 1 * WSZ, Wh + 2 * WSZ, Wh + 3 * WSZ,
            Wh + 4 * WSZ, Wh + 5 * WSZ, Wph + 0 * WPSZ, Wph + 1 * WPSZ };
        __nv_bfloat16* los[NSPLIT] = { xl, ctl, apl,
            Wl + 0 * WSZ, Wl + 1 * WSZ, Wl + 2 * WSZ, Wl + 3 * WSZ,
            Wl + 4 * WSZ, Wl + 5 * WSZ, Wpl + 0 * WPSZ, Wpl + 1 * WPSZ };
        const size_t ns[NSPLIT] = { (size_t)L1 * Hd, (size_t)L2 * Hd,
            (size_t)NF * L3 * CAd, WSZ, WSZ, WSZ, WSZ, WSZ, WSZ, WPSZ, WPSZ };
        int acc4 = 0;
        for (int i = 0; i < NSPLIT; i++) {
            sa.src[i] = (const float4*)srcs[i];
            sa.hi[i]  = (uint2*)his[i];
            sa.lo[i]  = (uint2*)los[i];
            acc4 += (int)(ns[i] / 4);
            sa.end[i] = acc4;
        }
        split_all_kernel<<<(acc4 + 255) / 256, 256>>>(sa);
    }

    const __nv_bfloat16* ctxth = cth + (size_t)IMG * Hd;
    const __nv_bfloat16* ctxtl = ctl + (size_t)IMG * Hd;

    // ---- 2) merged projection GEMM (Q first, then all context-side) ----
    {
        GemmArgs gaa;
        const int AM = NF * L3;   // 672
        int be = 0;
        auto set = [&](int i, const __nv_bfloat16* Ah_, const __nv_bfloat16* Al_,
                       const __nv_bfloat16* Bh_, const __nv_bfloat16* Bl_,
                       const float* bias_, float* Cf_,
                       __nv_bfloat16* Chp_, __nv_bfloat16* Clp_, int M_, int K_) {
            be += 12 * ((M_ + GBM - 1) / GBM);
            gaa.seg[i] = GemmSeg{ Ah_, Al_, Bh_, Bl_, bias_, Cf_, Chp_, Clp_,
                                  M_, K_, be };
        };
        set(0, xh,    xl,    Wh + 0 * WSZ,   Wl + 0 * WSZ,   bq,  gQ,      nullptr, nullptr, L1,   Hd);
        set(1, ctxth, ctxtl, Wh + 1 * WSZ,   Wl + 1 * WSZ,   bk,  gK,      nullptr, nullptr, LTXT, Hd);
        set(2, ctxth, ctxtl, Wh + 2 * WSZ,   Wl + 2 * WSZ,   bv,  nullptr, Vh,  Vl,  LTXT, Hd);
        set(3, cth,   ctl,   Wh + 3 * WSZ,   Wl + 3 * WSZ,   bki, gKi,     nullptr, nullptr, IMG,  Hd);
        set(4, cth,   ctl,   Wh + 4 * WSZ,   Wl + 4 * WSZ,   bvi, nullptr, Vih, Vil, IMG,  Hd);
        set(5, aph,   apl,   Wph + 0 * WPSZ, Wpl + 0 * WPSZ, nullptr, nullptr, PKh, PKl, NF * L3, CAd);
        set(6, aph,   apl,   Wph + 1 * WPSZ, Wpl + 1 * WPSZ, nullptr, nullptr, PVh, PVl, NF * L3, CAd);
        gemm_all<<<be, 256>>>(gaa);
    }

    // ---- 3) merged rmsnorm + split (Q, K, Kimg) ----
    rmsnorm_all<<<L1 + LTXT + IMG, 256>>>(
        gQ, nq, Qh, Ql, gK, nk, Kh, Kl, gKi, nki, Kih, Kil);

    // ---- 4) tensor-core fused attention -> bf16 hi/lo combined ----
    attn_mma<<<dim3(L1 / ATQ, NH), 128, ATTN_SMEM>>>(
        Qh, Ql, Kh, Kl, Vh, Vl, Kih, Kil, Vih, Vil, PKh, PKl, PVh, PVl,
        ctx_lens, audio_lens, Chh, Cll);

    // ---- 5) output projection ----
    gemm_pipe<<<dim3(Hd / GBN, L1 / GBM), 256>>>(
        Chh, Cll, Wh + 5 * WSZ, Wl + 5 * WSZ, bo, out, L1, Hd);
}

// round 16
// speedup vs baseline: 1.0472x; 1.0472x over previous
#include <cuda_runtime.h>
#include <cuda_bf16.h>
#include <math.h>

// ---------------------------------------------------------------------------
// Problem constants
// ---------------------------------------------------------------------------
#define L1   10752
#define NF   21
#define L2   769
#define IMG  257
#define LTXT 512          // L2 - IMG
#define Hd   1536
#define NH   12
#define Dh   128
#define L3   32
#define CAd  768
#define EPSV 1e-6f

// ---------------------------------------------------------------------------
// Scratch (static __device__ globals — allocation-free per harness rules)
// ---------------------------------------------------------------------------
__device__ float g_Q   [(size_t)L1 * Hd];
__device__ float g_K   [(size_t)LTXT * Hd];
__device__ float g_Kimg[(size_t)IMG * Hd];

__device__ __nv_bfloat16 g_xh [(size_t)L1 * Hd];
__device__ __nv_bfloat16 g_xl [(size_t)L1 * Hd];
__device__ __nv_bfloat16 g_cth[(size_t)L2 * Hd];
__device__ __nv_bfloat16 g_ctl[(size_t)L2 * Hd];
__device__ __nv_bfloat16 g_aph[(size_t)NF * L3 * CAd];
__device__ __nv_bfloat16 g_apl[(size_t)NF * L3 * CAd];
__device__ __nv_bfloat16 g_Wh [6][(size_t)Hd * Hd];   // q,k,v,ki,vi,o
__device__ __nv_bfloat16 g_Wl [6][(size_t)Hd * Hd];
__device__ __nv_bfloat16 g_Wph[2][(size_t)Hd * CAd];  // kp,vp
__device__ __nv_bfloat16 g_Wpl[2][(size_t)Hd * CAd];
__device__ __nv_bfloat16 g_Ch [(size_t)L1 * Hd];
__device__ __nv_bfloat16 g_Cl [(size_t)L1 * Hd];

__device__ __nv_bfloat16 g_Qh [(size_t)L1 * Hd];
__device__ __nv_bfloat16 g_Ql [(size_t)L1 * Hd];
__device__ __nv_bfloat16 g_Kh [(size_t)LTXT * Hd];
__device__ __nv_bfloat16 g_Kl [(size_t)LTXT * Hd];
__device__ __nv_bfloat16 g_Vh [(size_t)LTXT * Hd];
__device__ __nv_bfloat16 g_Vl [(size_t)LTXT * Hd];
__device__ __nv_bfloat16 g_Kih[(size_t)IMG * Hd];
__device__ __nv_bfloat16 g_Kil[(size_t)IMG * Hd];
__device__ __nv_bfloat16 g_Vih[(size_t)IMG * Hd];
__device__ __nv_bfloat16 g_Vil[(size_t)IMG * Hd];
__device__ __nv_bfloat16 g_PKh[(size_t)NF * L3 * Hd];
__device__ __nv_bfloat16 g_PKl[(size_t)NF * L3 * Hd];
__device__ __nv_bfloat16 g_PVh[(size_t)NF * L3 * Hd];
__device__ __nv_bfloat16 g_PVl[(size_t)NF * L3 * Hd];

// ---------------------------------------------------------------------------
// Helpers
// ---------------------------------------------------------------------------
__device__ __forceinline__ unsigned pack_bf16(__nv_bfloat16 lo, __nv_bfloat16 hi)
{
    return ((unsigned)__bfloat16_as_ushort(hi) << 16) | (unsigned)__bfloat16_as_ushort(lo);
}

__device__ __forceinline__ void mma_bf16(float* d, const unsigned* a, const unsigned* b)
{
    asm volatile(
        "mma.sync.aligned.m16n8k16.row.col.f32.bf16.bf16.f32 "
        "{%0,%1,%2,%3}, {%4,%5,%6,%7}, {%8,%9}, {%0,%1,%2,%3};\n"
        : "+f"(d[0]), "+f"(d[1]), "+f"(d[2]), "+f"(d[3])
        : "r"(a[0]), "r"(a[1]), "r"(a[2]), "r"(a[3]), "r"(b[0]), "r"(b[1]));
}

__device__ __forceinline__ void ldsm_x4(unsigned* r, const void* p)
{
    unsigned addr = (unsigned)__cvta_generic_to_shared(p);
    asm volatile(
        "ldmatrix.sync.aligned.m8n8.x4.shared.b16 {%0,%1,%2,%3}, [%4];\n"
        : "=r"(r[0]), "=r"(r[1]), "=r"(r[2]), "=r"(r[3]) : "r"(addr));
}

__device__ __forceinline__ void ldsm_x4_t(unsigned* r, const void* p)
{
    unsigned addr = (unsigned)__cvta_generic_to_shared(p);
    asm volatile(
        "ldmatrix.sync.aligned.m8n8.x4.trans.shared.b16 {%0,%1,%2,%3}, [%4];\n"
        : "=r"(r[0]), "=r"(r[1]), "=r"(r[2]), "=r"(r[3]) : "r"(addr));
}

__device__ __forceinline__ void cp_async16(void* dst, const void* src, int szbytes)
{
    unsigned d = (unsigned)__cvta_generic_to_shared(dst);
    asm volatile("cp.async.cg.shared.global [%0], [%1], 16, %2;\n"
                 :: "r"(d), "l"(src), "r"(szbytes));
}

__device__ __forceinline__ void split_pack2(float a, float b, unsigned& hi, unsigned& lo)
{
    __nv_bfloat16 ha = __float2bfloat16_rn(a);
    __nv_bfloat16 hb = __float2bfloat16_rn(b);
    hi = pack_bf16(ha, hb);
    lo = pack_bf16(__float2bfloat16_rn(a - __bfloat162float(ha)),
                   __float2bfloat16_rn(b - __bfloat162float(hb)));
}

// ---------------------------------------------------------------------------
// Merged elementwise split: all fp32 -> (hi, lo) bf16 passes in ONE launch
// ---------------------------------------------------------------------------
#define NSPLIT 11
struct SplitArgs {
    const float4* src[NSPLIT];
    uint2* hi[NSPLIT];
    uint2* lo[NSPLIT];
    int end[NSPLIT];          // prefix-sum (exclusive end) in float4 units
};

__global__ __launch_bounds__(256) void split_all_kernel(SplitArgs a)
{
    int i = blockIdx.x * 256 + threadIdx.x;
    if (i >= a.end[NSPLIT - 1]) return;
    int s = 0;
    while (i >= a.end[s]) s++;
    int base = (s == 0) ? 0 : a.end[s - 1];
    int li = i - base;
    float4 v = a.src[s][li];
    unsigned h0, l0, h1, l1;
    split_pack2(v.x, v.y, h0, l0);
    split_pack2(v.z, v.w, h1, l1);
    a.hi[s][li] = make_uint2(h0, h1);
    a.lo[s][li] = make_uint2(l0, l1);
}

// ---------------------------------------------------------------------------
// Merged RMSNorm (Q / K / Kimg) + hi/lo bf16 split output, ONE launch
// ---------------------------------------------------------------------------
__global__ __launch_bounds__(256) void rmsnorm_all(
    const float* __restrict__ XQ, const float* __restrict__ wq,
    __nv_bfloat16* __restrict__ QH, __nv_bfloat16* __restrict__ QL,
    const float* __restrict__ XK, const float* __restrict__ wk,
    __nv_bfloat16* __restrict__ KH, __nv_bfloat16* __restrict__ KL,
    const float* __restrict__ XI, const float* __restrict__ wi,
    __nv_bfloat16* __restrict__ IH, __nv_bfloat16* __restrict__ IL)
{
    int row = blockIdx.x;
    const float *X, *w;
    __nv_bfloat16 *H, *Lo;
    if (row < L1)              { X = XQ; w = wq; H = QH; Lo = QL; }
    else if (row < L1 + LTXT)  { row -= L1; X = XK; w = wk; H = KH; Lo = KL; }
    else                       { row -= L1 + LTXT; X = XI; w = wi; H = IH; Lo = IL; }

    const float* x = X + (size_t)row * Hd;
    const int tid = threadIdx.x;

    float v[6];
    float ss = 0.f;
#pragma unroll
    for (int i = 0; i < 6; i++) {
        v[i] = x[tid + i * 256];
        ss = fmaf(v[i], v[i], ss);
    }
#pragma unroll
    for (int o = 16; o > 0; o >>= 1) ss += __shfl_xor_sync(0xffffffffu, ss, o);

    __shared__ float warp_s[8];
    __shared__ float s_scale;
    if ((tid & 31) == 0) warp_s[tid >> 5] = ss;
    __syncthreads();
    if (tid < 8) {
        float t = warp_s[tid];
#pragma unroll
        for (int o = 4; o > 0; o >>= 1) t += __shfl_xor_sync(0xffu, t, o);
        if (tid == 0) s_scale = rsqrtf(t * (1.f / (float)Hd) + EPSV);
    }
    __syncthreads();
    float sc = s_scale;
#pragma unroll
    for (int i = 0; i < 6; i++) {
        int c = tid + i * 256;
        float f = v[i] * sc * w[c];
        __nv_bfloat16 h = __float2bfloat16_rn(f);
        H[(size_t)row * Hd + c]  = h;
        Lo[(size_t)row * Hd + c] = __float2bfloat16_rn(f - __bfloat162float(h));
    }
}

// ---------------------------------------------------------------------------
// Tensor-core GEMM body (bf16x3), GBK=32, cp.async double-buffered.
// MMA issue is variant-outer: consecutive MMAs hit different accumulators
// (dependency distance 16) to avoid HMMA RAW stalls.
// ---------------------------------------------------------------------------
#define GBM 128
#define GBN 128
#define GBK 32
#define TILE_E (GBM * GBK)

__device__ __forceinline__ int swz32(int r, int k)
{
    return r * GBK + ((((k >> 3) ^ (r >> 1)) & 3) << 3) + (k & 7);
}

struct GemmAcc { float a[2][8][4]; };

__device__ __forceinline__ void gemm_body(
    const __nv_bfloat16* __restrict__ Ah, const __nv_bfloat16* __restrict__ Al,
    const __nv_bfloat16* __restrict__ Bh, const __nv_bfloat16* __restrict__ Bl,
    int M, int K, int bm, int bn, GemmAcc& acc,
    __nv_bfloat16 (*s)[4][TILE_E])
{
    const int tid  = threadIdx.x;
    const int warp = tid >> 5;
    const int lane = tid & 31;
    const int wm   = warp >> 1;
    const int wn   = warp & 1;

    const int lr   = tid >> 1;
    const int lcp  = (tid & 1) << 4;
    const int o0   = swz32(lr, lcp);
    const int o1   = swz32(lr, lcp + 8);
    const bool va  = (bm + lr) < M;
    const int  ra  = va ? (bm + lr) : 0;
    const int  rb  = bn + lr;
    const int  sza = va ? 16 : 0;

#pragma unroll
    for (int i = 0; i < 2; i++)
#pragma unroll
        for (int j = 0; j < 8; j++)
#pragma unroll
            for (int t = 0; t < 4; t++) acc.a[i][j][t] = 0.f;

    const int nt = K / GBK;

    {
        const __nv_bfloat16* pa = Ah + (size_t)ra * K + lcp;
        const __nv_bfloat16* pl = Al + (size_t)ra * K + lcp;
        const __nv_bfloat16* pb = Bh + (size_t)rb * K + lcp;
        const __nv_bfloat16* pc = Bl + (size_t)rb * K + lcp;
        cp_async16(&s[0][0][o0], pa,     sza);
        cp_async16(&s[0][0][o1], pa + 8, sza);
        cp_async16(&s[0][1][o0], pl,     sza);
        cp_async16(&s[0][1][o1], pl + 8, sza);
        cp_async16(&s[0][2][o0], pb,     16);
        cp_async16(&s[0][2][o1], pb + 8, 16);
        cp_async16(&s[0][3][o0], pc,     16);
        cp_async16(&s[0][3][o1], pc + 8, 16);
        asm volatile("cp.async.commit_group;\n" ::: "memory");
    }

    const int rfrg = lane & 15;
    const int kfo  = (lane >> 4) << 3;

    for (int t = 0; t < nt; t++) {
        if (t + 1 < nt) {
            const int st = (t + 1) & 1;
            const int k0 = (t + 1) * GBK;
            const __nv_bfloat16* pa = Ah + (size_t)ra * K + k0 + lcp;
            const __nv_bfloat16* pl = Al + (size_t)ra * K + k0 + lcp;
            const __nv_bfloat16* pb = Bh + (size_t)rb * K + k0 + lcp;
            const __nv_bfloat16* pc = Bl + (size_t)rb * K + k0 + lcp;
            cp_async16(&s[st][0][o0], pa,     sza);
            cp_async16(&s[st][0][o1], pa + 8, sza);
            cp_async16(&s[st][1][o0], pl,     sza);
            cp_async16(&s[st][1][o1], pl + 8, sza);
            cp_async16(&s[st][2][o0], pb,     16);
            cp_async16(&s[st][2][o1], pb + 8, 16);
            cp_async16(&s[st][3][o0], pc,     16);
            cp_async16(&s[st][3][o1], pc + 8, 16);
            asm volatile("cp.async.commit_group;\n" ::: "memory");
            asm volatile("cp.async.wait_group 1;\n" ::: "memory");
        } else {
            asm volatile("cp.async.wait_group 0;\n" ::: "memory");
        }
        __syncthreads();

        const __nv_bfloat16* pAh = s[t & 1][0];
        const __nv_bfloat16* pAl = s[t & 1][1];
        const __nv_bfloat16* pBh = s[t & 1][2];
        const __nv_bfloat16* pBl = s[t & 1][3];

#pragma unroll
        for (int ks = 0; ks < 2; ks++) {
            const int kf = ks * 16 + kfo;

            unsigned ah[2][4], al[2][4];
#pragma unroll
            for (int i = 0; i < 2; i++) {
                int r = wm * 32 + i * 16 + rfrg;
                ldsm_x4(ah[i], pAh + swz32(r, kf));
                ldsm_x4(al[i], pAl + swz32(r, kf));
            }

            unsigned bh[8][2], bl[8][2];
#pragma unroll
            for (int p = 0; p < 4; p++) {
                int n = wn * 64 + p * 16 + rfrg;
                unsigned tt[4];
                ldsm_x4(tt, pBh + swz32(n, kf));
                bh[p*2][0] = tt[0]; bh[p*2+1][0] = tt[1];
                bh[p*2][1] = tt[2]; bh[p*2+1][1] = tt[3];
                ldsm_x4(tt, pBl + swz32(n, kf));
                bl[p*2][0] = tt[0]; bl[p*2+1][0] = tt[1];
                bl[p*2][1] = tt[2]; bl[p*2+1][1] = tt[3];
            }

            // variant-outer issue: 16 independent MMAs between accumulator reuses
#pragma unroll
            for (int i = 0; i < 2; i++)
#pragma unroll
                for (int j = 0; j < 8; j++)
                    mma_bf16(acc.a[i][j], ah[i], bh[j]);
#pragma unroll
            for (int i = 0; i < 2; i++)
#pragma unroll
                for (int j = 0; j < 8; j++)
                    mma_bf16(acc.a[i][j], ah[i], bl[j]);
#pragma unroll
            for (int i = 0; i < 2; i++)
#pragma unroll
                for (int j = 0; j < 8; j++)
                    mma_bf16(acc.a[i][j], al[i], bh[j]);
        }
        __syncthreads();
    }
}

// ---------------------------------------------------------------------------
// Merged projection GEMM: 7 segments in one launch (Q first).
// ---------------------------------------------------------------------------
#define NGSEG 7
struct GemmSeg {
    const __nv_bfloat16 *Ah, *Al, *Bh, *Bl;
    const float* bias;
    float* Cf;                       // fp32 out (else split out)
    __nv_bfloat16 *Chp, *Clp;
    int M, K, blk_end;
};
struct GemmArgs { GemmSeg seg[NGSEG]; };

__global__ __launch_bounds__(256) void gemm_all(GemmArgs ga)
{
    __shared__ __nv_bfloat16 s[2][4][TILE_E];

    int sidx = 0;
    while ((int)blockIdx.x >= ga.seg[sidx].blk_end) sidx++;
    const GemmSeg& g = ga.seg[sidx];
    const int base  = (sidx == 0) ? 0 : ga.seg[sidx - 1].blk_end;
    const int local = blockIdx.x - base;
    const int bm = (local / 12) * GBM;
    const int bn = (local % 12) * GBN;

    GemmAcc acc;
    gemm_body(g.Ah, g.Al, g.Bh, g.Bl, g.M, g.K, bm, bn, acc, s);

    const int lane = threadIdx.x & 31;
    const int warp = threadIdx.x >> 5;
    const int wm = warp >> 1, wn = warp & 1;

#pragma unroll
    for (int i = 0; i < 2; i++) {
        int r0 = bm + wm * 32 + i * 16 + (lane >> 2);
        int r1 = r0 + 8;
#pragma unroll
        for (int j = 0; j < 8; j++) {
            int c  = bn + wn * 64 + j * 8 + (lane & 3) * 2;
            float b0 = g.bias ? g.bias[c]     : 0.f;
            float b1 = g.bias ? g.bias[c + 1] : 0.f;
            float v0 = acc.a[i][j][0] + b0, v1 = acc.a[i][j][1] + b1;
            float v2 = acc.a[i][j][2] + b0, v3 = acc.a[i][j][3] + b1;
            if (g.Cf) {
                if (r0 < g.M) {
                    g.Cf[(size_t)r0 * Hd + c]     = v0;
                    g.Cf[(size_t)r0 * Hd + c + 1] = v1;
                }
                if (r1 < g.M) {
                    g.Cf[(size_t)r1 * Hd + c]     = v2;
                    g.Cf[(size_t)r1 * Hd + c + 1] = v3;
                }
            } else {
                unsigned hi, lo;
                if (r0 < g.M) {
                    split_pack2(v0, v1, hi, lo);
                    *(unsigned*)&g.Chp[(size_t)r0 * Hd + c] = hi;
                    *(unsigned*)&g.Clp[(size_t)r0 * Hd + c] = lo;
                }
                if (r1 < g.M) {
                    split_pack2(v2, v3, hi, lo);
                    *(unsigned*)&g.Chp[(size_t)r1 * Hd + c] = hi;
                    *(unsigned*)&g.Clp[(size_t)r1 * Hd + c] = lo;
                }
            }
        }
    }
}

// Standalone GEMM for the O-projection (fp32 out).
__global__ __launch_bounds__(256) void gemm_pipe(
    const __nv_bfloat16* __restrict__ Ah, const __nv_bfloat16* __restrict__ Al,
    const __nv_bfloat16* __restrict__ Bh, const __nv_bfloat16* __restrict__ Bl,
    const float* __restrict__ bias, float* __restrict__ C,
    int M, int K)
{
    __shared__ __nv_bfloat16 s[2][4][TILE_E];
    const int bm = blockIdx.y * GBM;
    const int bn = blockIdx.x * GBN;

    GemmAcc acc;
    gemm_body(Ah, Al, Bh, Bl, M, K, bm, bn, acc, s);

    const int lane = threadIdx.x & 31;
    const int warp = threadIdx.x >> 5;
    const int wm = warp >> 1, wn = warp & 1;

#pragma unroll
    for (int i = 0; i < 2; i++) {
        int r0 = bm + wm * 32 + i * 16 + (lane >> 2);
        int r1 = r0 + 8;
#pragma unroll
        for (int j = 0; j < 8; j++) {
            int c  = bn + wn * 64 + j * 8 + (lane & 3) * 2;
            float b0 = bias ? bias[c]     : 0.f;
            float b1 = bias ? bias[c + 1] : 0.f;
            if (r0 < M) {
                C[(size_t)r0 * Hd + c]     = acc.a[i][j][0] + b0;
                C[(size_t)r0 * Hd + c + 1] = acc.a[i][j][1] + b1;
            }
            if (r1 < M) {
                C[(size_t)r1 * Hd + c]     = acc.a[i][j][2] + b0;
                C[(size_t)r1 * Hd + c + 1] = acc.a[i][j][3] + b1;
            }
        }
    }
}

// ---------------------------------------------------------------------------
// Tensor-core fused 3-phase flash attention, with dependency-spread MMA issue.
// grid = (L1/64, NH), block = 128 (4 warps x 16 query rows).
// ---------------------------------------------------------------------------
#define ATQ 64
#define ASTR 132
#define AQ_ELE (64 * 128)
#define AKV_ELE (32 * 128)
#define ATTN_SMEM ((2 * AQ_ELE + 8 * AKV_ELE) * 2)   // 96 KB

__device__ __forceinline__ int soff(int r, int c8)
{
    return r * 128 + (((c8) ^ (r & 7)) << 3);
}

__global__ __launch_bounds__(128) void attn_mma(
    const __nv_bfloat16* __restrict__ Qh,  const __nv_bfloat16* __restrict__ Ql,
    const __nv_bfloat16* __restrict__ Kth, const __nv_bfloat16* __restrict__ Ktl,
    const __nv_bfloat16* __restrict__ Vth, const __nv_bfloat16* __restrict__ Vtl,
    const __nv_bfloat16* __restrict__ Kih, const __nv_bfloat16* __restrict__ Kil,
    const __nv_bfloat16* __restrict__ Vih, const __nv_bfloat16* __restrict__ Vil,
    const __nv_bfloat16* __restrict__ PKh, const __nv_bfloat16* __restrict__ PKl,
    const __nv_bfloat16* __restrict__ PVh, const __nv_bfloat16* __restrict__ PVl,
    const int* __restrict__ ctx_lens, const int* __restrict__ audio_lens,
    __nv_bfloat16* __restrict__ Ch, __nv_bfloat16* __restrict__ Cl)
{
    extern __shared__ __nv_bfloat16 sm[];
    __nv_bfloat16* sQh = sm;
    __nv_bfloat16* sQl = sQh + AQ_ELE;
    __nv_bfloat16* sKV = sQl + AQ_ELE;

    const int head  = blockIdx.y;
    const int qbase = blockIdx.x * ATQ;
    const int tid   = threadIdx.x;
    const int warp  = tid >> 5;
    const int lane  = tid & 31;
    const int g     = lane >> 2;
    const int tq    = lane & 3;
    const float scale = 0.08838834764831845f;

#pragma unroll
    for (int i = 0; i < 8; i++) {
        int idx = tid + i * 128;
        int r = idx >> 4, c8 = idx & 15;
        size_t go = (size_t)(qbase + r) * Hd + head * Dh + c8 * 8;
        int so = soff(r, c8);
        *(uint4*)&sQh[so] = *(const uint4*)&Qh[go];
        *(uint4*)&sQl[so] = *(const uint4*)&Ql[go];
    }
    __syncthreads();

    float G[16][4];
#pragma unroll
    for (int n = 0; n < 16; n++)
#pragma unroll
        for (int e = 0; e < 4; e++) G[n][e] = 0.f;

    const int frame   = qbase >> 9;
    const int txt_len = ctx_lens[0];
    const int rfrg = lane & 15;
    const int chi  = lane >> 4;

    for (int phase = 0; phase < 3; phase++) {
        const __nv_bfloat16 *KH, *KL, *VH, *VL;
        int klen;
        if (phase == 0)      { KH = Kih; KL = Kil; VH = Vih; VL = Vil; klen = IMG; }
        else if (phase == 1) { KH = Kth; KL = Ktl; VH = Vth; VL = Vtl; klen = txt_len; }
        else {
            size_t fo = (size_t)frame * L3 * Hd;
            KH = PKh + fo; KL = PKl + fo; VH = PVh + fo; VL = PVl + fo;
            klen = audio_lens[frame];
        }
        const int nch = (klen + 31) >> 5;

        {
            const int cl = min(32, klen);
#pragma unroll
            for (int a = 0; a < 4; a++) {
                const __nv_bfloat16* src = (a == 0) ? KH : (a == 1) ? KL
                                         : (a == 2) ? VH : VL;
#pragma unroll
                for (int i = 0; i < 4; i++) {
                    int idx = tid + i * 128;
                    int r = idx >> 4, c8 = idx & 15;
                    int grow = (r < cl) ? r : 0;
                    cp_async16(&sKV[a * AKV_ELE + soff(r, c8)],
                               src + (size_t)grow * Hd + head * Dh + c8 * 8,
                               r < cl ? 16 : 0);
                }
            }
            asm volatile("cp.async.commit_group;\n" ::: "memory");
        }

        float m0 = -1e30f, m1 = -1e30f, l0 = 0.f, l1 = 0.f;
        float o[16][4];
#pragma unroll
        for (int n = 0; n < 16; n++)
#pragma unroll
            for (int e = 0; e < 4; e++) o[n][e] = 0.f;

        for (int c = 0; c < nch; c++) {
            const int b = c & 1;
            if (c + 1 < nch) {
                const int kb2 = (c + 1) * 32;
                const int cl2 = min(32, klen - kb2);
#pragma unroll
                for (int a = 0; a < 4; a++) {
                    const __nv_bfloat16* src = (a == 0) ? KH : (a == 1) ? KL
                                             : (a == 2) ? VH : VL;
#pragma unroll
                    for (int i = 0; i < 4; i++) {
                        int idx = tid + i * 128;
                        int r = idx >> 4, c8 = idx & 15;
                        int grow = (r < cl2) ? kb2 + r : 0;
                        cp_async16(&sKV[((b ^ 1) * 4 + a) * AKV_ELE + soff(r, c8)],
                                   src + (size_t)grow * Hd + head * Dh + c8 * 8,
                                   r < cl2 ? 16 : 0);
                    }
                }
                asm volatile("cp.async.commit_group;\n" ::: "memory");
                asm volatile("cp.async.wait_group 1;\n" ::: "memory");
            } else {
                asm volatile("cp.async.wait_group 0;\n" ::: "memory");
            }
            __syncthreads();

            const __nv_bfloat16* pKh = sKV + (b * 4 + 0) * AKV_ELE;
            const __nv_bfloat16* pKl = sKV + (b * 4 + 1) * AKV_ELE;
            const __nv_bfloat16* pVh = sKV + (b * 4 + 2) * AKV_ELE;
            const __nv_bfloat16* pVl = sKV + (b * 4 + 3) * AKV_ELE;
            const int kb = c * 32;

            float sacc[4][4];
#pragma unroll
            for (int n = 0; n < 4; n++)
#pragma unroll
                for (int e = 0; e < 4; e++) sacc[n][e] = 0.f;

#pragma unroll
            for (int ks = 0; ks < 8; ks++) {
                const int c8 = ks * 2 + chi;
                unsigned aqh[4], aql[4];
                ldsm_x4(aqh, &sQh[soff(warp * 16 + rfrg, c8)]);
                ldsm_x4(aql, &sQl[soff(warp * 16 + rfrg, c8)]);

                unsigned kbh[4][2], kbl[4][2];
#pragma unroll
                for (int p = 0; p < 2; p++) {
                    unsigned t[4];
                    ldsm_x4(t, &pKh[soff(p * 16 + rfrg, c8)]);
                    kbh[p*2][0] = t[0]; kbh[p*2+1][0] = t[1];
                    kbh[p*2][1] = t[2]; kbh[p*2+1][1] = t[3];
                    ldsm_x4(t, &pKl[soff(p * 16 + rfrg, c8)]);
                    kbl[p*2][0] = t[0]; kbl[p*2+1][0] = t[1];
                    kbl[p*2][1] = t[2]; kbl[p*2+1][1] = t[3];
                }
                // variant-outer: dependency distance 4
#pragma unroll
                for (int n = 0; n < 4; n++) mma_bf16(sacc[n], aqh, kbh[n]);
#pragma unroll
                for (int n = 0; n < 4; n++) mma_bf16(sacc[n], aqh, kbl[n]);
#pragma unroll
                for (int n = 0; n < 4; n++) mma_bf16(sacc[n], aql, kbh[n]);
            }

            float rmax0 = -1e30f, rmax1 = -1e30f;
#pragma unroll
            for (int n = 0; n < 4; n++) {
                int colb = kb + n * 8 + tq * 2;
                bool v0 = colb < klen, v1 = (colb + 1) < klen;
                float x0 = v0 ? sacc[n][0] * scale : -1e30f;
                float x1 = v1 ? sacc[n][1] * scale : -1e30f;
                float x2 = v0 ? sacc[n][2] * scale : -1e30f;
                float x3 = v1 ? sacc[n][3] * scale : -1e30f;
                sacc[n][0] = x0; sacc[n][1] = x1; sacc[n][2] = x2; sacc[n][3] = x3;
                rmax0 = fmaxf(rmax0, fmaxf(x0, x1));
                rmax1 = fmaxf(rmax1, fmaxf(x2, x3));
            }
            rmax0 = fmaxf(rmax0, __shfl_xor_sync(0xffffffffu, rmax0, 1));
            rmax0 = fmaxf(rmax0, __shfl_xor_sync(0xffffffffu, rmax0, 2));
            rmax1 = fmaxf(rmax1, __shfl_xor_sync(0xffffffffu, rmax1, 1));
            rmax1 = fmaxf(rmax1, __shfl_xor_sync(0xffffffffu, rmax1, 2));

            float mn0 = fmaxf(m0, rmax0), mn1 = fmaxf(m1, rmax1);
            float c0 = __expf(m0 - mn0),  c1 = __expf(m1 - mn1);
            float s0 = 0.f, s1 = 0.f;
#pragma unroll
            for (int n = 0; n < 4; n++) {
                float p0 = __expf(sacc[n][0] - mn0);
                float p1 = __expf(sacc[n][1] - mn0);
                float p2 = __expf(sacc[n][2] - mn1);
                float p3 = __expf(sacc[n][3] - mn1);
                sacc[n][0] = p0; sacc[n][1] = p1; sacc[n][2] = p2; sacc[n][3] = p3;
                s0 += p0 + p1; s1 += p2 + p3;
            }
            s0 += __shfl_xor_sync(0xffffffffu, s0, 1);
            s0 += __shfl_xor_sync(0xffffffffu, s0, 2);
            s1 += __shfl_xor_sync(0xffffffffu, s1, 1);
            s1 += __shfl_xor_sync(0xffffffffu, s1, 2);
            l0 = l0 * c0 + s0; l1 = l1 * c1 + s1;
            m0 = mn0; m1 = mn1;

#pragma unroll
            for (int n = 0; n < 16; n++) {
                o[n][0] *= c0; o[n][1] *= c0;
                o[n][2] *= c1; o[n][3] *= c1;
            }

            unsigned aPh[2][4], aPl[2][4];
#pragma unroll
            for (int ks = 0; ks < 2; ks++) {
                split_pack2(sacc[2*ks][0],   sacc[2*ks][1],   aPh[ks][0], aPl[ks][0]);
                split_pack2(sacc[2*ks][2],   sacc[2*ks][3],   aPh[ks][1], aPl[ks][1]);
                split_pack2(sacc[2*ks+1][0], sacc[2*ks+1][1], aPh[ks][2], aPl[ks][2]);
                split_pack2(sacc[2*ks+1][2], sacc[2*ks+1][3], aPh[ks][3], aPl[ks][3]);
            }

#pragma unroll
            for (int ks = 0; ks < 2; ks++) {
#pragma unroll
                for (int ntp = 0; ntp < 8; ntp++) {
                    int vr = ks * 16 + ((lane >> 3) & 1) * 8 + (lane & 7);
                    int vc = ntp * 2 + (lane >> 4);
                    unsigned th[4], tl[4];
                    ldsm_x4_t(th, &pVh[soff(vr, vc)]);
                    ldsm_x4_t(tl, &pVl[soff(vr, vc)]);
                    unsigned bh0[2] = {th[0], th[1]};
                    unsigned bh1[2] = {th[2], th[3]};
                    unsigned bl0[2] = {tl[0], tl[1]};
                    unsigned bl1[2] = {tl[2], tl[3]};
                    // interleave even/odd output tiles: dependency distance 2
                    mma_bf16(o[2*ntp],   aPh[ks], bh0);
                    mma_bf16(o[2*ntp+1], aPh[ks], bh1);
                    mma_bf16(o[2*ntp],   aPh[ks], bl0);
                    mma_bf16(o[2*ntp+1], aPh[ks], bl1);
                    mma_bf16(o[2*ntp],   aPl[ks], bh0);
                    mma_bf16(o[2*ntp+1], aPl[ks], bh1);
                }
            }
            __syncthreads();
        }

        float rl0 = 1.f / l0, rl1 = 1.f / l1;
#pragma unroll
        for (int n = 0; n < 16; n++) {
            G[n][0] += o[n][0] * rl0; G[n][1] += o[n][1] * rl0;
            G[n][2] += o[n][2] * rl1; G[n][3] += o[n][3] * rl1;
        }
    }

    float* sO = (float*)sKV;
    {
        int row0 = warp * 16 + g;
#pragma unroll
        for (int n = 0; n < 16; n++) {
            int col = n * 8 + tq * 2;
            sO[row0 * ASTR + col]           = G[n][0];
            sO[row0 * ASTR + col + 1]       = G[n][1];
            sO[(row0 + 8) * ASTR + col]     = G[n][2];
            sO[(row0 + 8) * ASTR + col + 1] = G[n][3];
        }
    }
    __syncthreads();
#pragma unroll
    for (int i = 0; i < 16; i++) {
        int idx = tid + i * 128;
        int r = idx >> 5, cb = (idx & 31) * 4;
        float f0 = sO[r * ASTR + cb + 0];
        float f1 = sO[r * ASTR + cb + 1];
        float f2 = sO[r * ASTR + cb + 2];
        float f3 = sO[r * ASTR + cb + 3];
        unsigned h0, l0u, h1, l1u;
        split_pack2(f0, f1, h0, l0u);
        split_pack2(f2, f3, h1, l1u);
        size_t go = (size_t)(qbase + r) * Hd + head * Dh + cb;
        *(uint2*)&Ch[go] = make_uint2(h0, h1);
        *(uint2*)&Cl[go] = make_uint2(l0u, l1u);
    }
}

// ---------------------------------------------------------------------------
// Launch
// ---------------------------------------------------------------------------
extern "C" void kernel_launch(void* const* d_in, const int* in_sizes, int n_in,
                              void* d_out, int out_size)
{
    const float* x          = (const float*)d_in[0];
    const float* context    = (const float*)d_in[1];
    const float* audio_proj = (const float*)d_in[2];
    const float* Wq  = (const float*)d_in[3];
    const float* bq  = (const float*)d_in[4];
    const float* Wk  = (const float*)d_in[5];
    const float* bk  = (const float*)d_in[6];
    const float* Wv  = (const float*)d_in[7];
    const float* bv  = (const float*)d_in[8];
    const float* Wki = (const float*)d_in[9];
    const float* bki = (const float*)d_in[10];
    const float* Wvi = (const float*)d_in[11];
    const float* bvi = (const float*)d_in[12];
    const float* Wo  = (const float*)d_in[13];
    const float* bo  = (const float*)d_in[14];
    const float* nq  = (const float*)d_in[15];
    const float* nk  = (const float*)d_in[16];
    const float* nki = (const float*)d_in[17];
    const float* Wkp = (const float*)d_in[18];
    const float* Wvp = (const float*)d_in[19];
    const int* ctx_lens   = (const int*)d_in[20];
    const int* audio_lens = (const int*)d_in[21];
    float* out = (float*)d_out;

    float *gQ, *gK, *gKi;
    cudaGetSymbolAddress((void**)&gQ,  g_Q);
    cudaGetSymbolAddress((void**)&gK,  g_K);
    cudaGetSymbolAddress((void**)&gKi, g_Kimg);

    __nv_bfloat16 *xh, *xl, *cth, *ctl, *aph, *apl, *Wh, *Wl, *Wph, *Wpl, *Chh, *Cll;
    cudaGetSymbolAddress((void**)&xh,  g_xh);
    cudaGetSymbolAddress((void**)&xl,  g_xl);
    cudaGetSymbolAddress((void**)&cth, g_cth);
    cudaGetSymbolAddress((void**)&ctl, g_ctl);
    cudaGetSymbolAddress((void**)&aph, g_aph);
    cudaGetSymbolAddress((void**)&apl, g_apl);
    cudaGetSymbolAddress((void**)&Wh,  g_Wh);
    cudaGetSymbolAddress((void**)&Wl,  g_Wl);
    cudaGetSymbolAddress((void**)&Wph, g_Wph);
    cudaGetSymbolAddress((void**)&Wpl, g_Wpl);
    cudaGetSymbolAddress((void**)&Chh, g_Ch);
    cudaGetSymbolAddress((void**)&Cll, g_Cl);

    __nv_bfloat16 *Qh, *Ql, *Kh, *Kl, *Vh, *Vl, *Kih, *Kil, *Vih, *Vil,
                  *PKh, *PKl, *PVh, *PVl;
    cudaGetSymbolAddress((void**)&Qh,  g_Qh);
    cudaGetSymbolAddress((void**)&Ql,  g_Ql);
    cudaGetSymbolAddress((void**)&Kh,  g_Kh);
    cudaGetSymbolAddress((void**)&Kl,  g_Kl);
    cudaGetSymbolAddress((void**)&Vh,  g_Vh);
    cudaGetSymbolAddress((void**)&Vl,  g_Vl);
    cudaGetSymbolAddress((void**)&Kih, g_Kih);
    cudaGetSymbolAddress((void**)&Kil, g_Kil);
    cudaGetSymbolAddress((void**)&Vih, g_Vih);
    cudaGetSymbolAddress((void**)&Vil, g_Vil);
    cudaGetSymbolAddress((void**)&PKh, g_PKh);
    cudaGetSymbolAddress((void**)&PKl, g_PKl);
    cudaGetSymbolAddress((void**)&PVh, g_PVh);
    cudaGetSymbolAddress((void**)&PVl, g_PVl);

    cudaFuncSetAttribute(attn_mma, cudaFuncAttributeMaxDynamicSharedMemorySize,
                         ATTN_SMEM);

    const size_t WSZ  = (size_t)Hd * Hd;
    const size_t WPSZ = (size_t)Hd * CAd;

    // ---- 1) merged split of all fp32 operands ----
    {
        SplitArgs sa;
        const float* srcs[NSPLIT] = { x, context, audio_proj,
                                      Wq, Wk, Wv, Wki, Wvi, Wo, Wkp, Wvp };
        __nv_bfloat16* his[NSPLIT] = { xh, cth, aph,
            Wh + 0 * WSZ, Wh + 1 * WSZ, Wh + 2 * WSZ, Wh + 3 * WSZ,
            Wh + 4 * WSZ, Wh + 5 * WSZ, Wph + 0 * WPSZ, Wph + 1 * WPSZ };
        __nv_bfloat16* los[NSPLIT] = { xl, ctl, apl,
            Wl + 0 * WSZ, Wl + 1 * WSZ, Wl + 2 * WSZ, Wl + 3 * WSZ,
            Wl + 4 * WSZ, Wl + 5 * WSZ, Wpl + 0 * WPSZ, Wpl + 1 * WPSZ };
        const size_t ns[NSPLIT] = { (size_t)L1 * Hd, (size_t)L2 * Hd,
            (size_t)NF * L3 * CAd, WSZ, WSZ, WSZ, WSZ, WSZ, WSZ, WPSZ, WPSZ };
        int acc4 = 0;
        for (int i = 0; i < NSPLIT; i++) {
            sa.src[i] = (const float4*)srcs[i];
            sa.hi[i]  = (uint2*)his[i];
            sa.lo[i]  = (uint2*)los[i];
            acc4 += (int)(ns[i] / 4);
            sa.end[i] = acc4;
        }
        split_all_kernel<<<(acc4 + 255) / 256, 256>>>(sa);
    }

    const __nv_bfloat16* ctxth = cth + (size_t)IMG * Hd;
    const __nv_bfloat16* ctxtl = ctl + (size_t)IMG * Hd;

    // ---- 2) merged projection GEMM (Q first, then all context-side) ----
    {
        GemmArgs gaa;
        int be = 0;
        auto set = [&](int i, const __nv_bfloat16* Ah_, const __nv_bfloat16* Al_,
                       const __nv_bfloat16* Bh_, const __nv_bfloat16* Bl_,
                       const float* bias_, float* Cf_,
                       __nv_bfloat16* Chp_, __nv_bfloat16* Clp_, int M_, int K_) {
            be += 12 * ((M_ + GBM - 1) / GBM);
            gaa.seg[i] = GemmSeg{ Ah_, Al_, Bh_, Bl_, bias_, Cf_, Chp_, Clp_,
                                  M_, K_, be };
        };
        set(0, xh,    xl,    Wh + 0 * WSZ,   Wl + 0 * WSZ,   bq,  gQ,      nullptr, nullptr, L1,   Hd);
        set(1, ctxth, ctxtl, Wh + 1 * WSZ,   Wl + 1 * WSZ,   bk,  gK,      nullptr, nullptr, LTXT, Hd);
        set(2, ctxth, ctxtl, Wh + 2 * WSZ,   Wl + 2 * WSZ,   bv,  nullptr, Vh,  Vl,  LTXT, Hd);
        set(3, cth,   ctl,   Wh + 3 * WSZ,   Wl + 3 * WSZ,   bki, gKi,     nullptr, nullptr, IMG,  Hd);
        set(4, cth,   ctl,   Wh + 4 * WSZ,   Wl + 4 * WSZ,   bvi, nullptr, Vih, Vil, IMG,  Hd);
        set(5, aph,   apl,   Wph + 0 * WPSZ, Wpl + 0 * WPSZ, nullptr, nullptr, PKh, PKl, NF * L3, CAd);
        set(6, aph,   apl,   Wph + 1 * WPSZ, Wpl + 1 * WPSZ, nullptr, nullptr, PVh, PVl, NF * L3, CAd);
        gemm_all<<<be, 256>>>(gaa);
    }

    // ---- 3) merged rmsnorm + split (Q, K, Kimg) ----
    rmsnorm_all<<<L1 + LTXT + IMG, 256>>>(
        gQ, nq, Qh, Ql, gK, nk, Kh, Kl, gKi, nki, Kih, Kil);

    // ---- 4) tensor-core fused attention -> bf16 hi/lo combined ----
    attn_mma<<<dim3(L1 / ATQ, NH), 128, ATTN_SMEM>>>(
        Qh, Ql, Kh, Kl, Vh, Vl, Kih, Kil, Vih, Vil, PKh, PKl, PVh, PVl,
        ctx_lens, audio_lens, Chh, Cll);

    // ---- 5) output projection ----
    gemm_pipe<<<dim3(Hd / GBN, L1 / GBM), 256>>>(
        Chh, Cll, Wh + 5 * WSZ, Wl + 5 * WSZ, bo, out, L1, Hd);
}